// round 13
// baseline (speedup 1.0000x reference)
#include <cuda_runtime.h>
#include <cuda_fp16.h>
#include <math.h>

#define C   128
#define HW  1024
#define N   4096
#define K   128
#define INV_TEMP (1.0f/0.07f)

// Scratch: normalized row-major [N, C] fp16 features (1 MB each).
__device__ __align__(16) __half g_qh[N * C];
__device__ __align__(16) __half g_kh[N * C];

// One block per (tensor p, batch b, 32-wide hw chunk): 2*4*32 = 256 blocks.
__global__ void normalize_kernel(const float* __restrict__ fq,
                                 const float* __restrict__ fk,
                                 float* __restrict__ out) {
    __shared__ float s[C][33];
    __shared__ float ps[8][32];
    __shared__ float inv[32];

    if (blockIdx.x == 0 && threadIdx.x == 0) out[0] = 0.0f;

    const int p   = blockIdx.x >> 7;          // 0 = q, 1 = k
    const int b   = (blockIdx.x >> 5) & 3;
    const int hw0 = (blockIdx.x & 31) << 5;
    const int t   = threadIdx.x;

    const float* src = (p == 0 ? fq : fk) + (size_t)b * C * HW + hw0;

    #pragma unroll
    for (int iter = 0; iter < 16; iter++) {
        int e = t + iter * 256;
        int c = e >> 5, i = e & 31;
        s[c][i] = src[c * HW + i];
    }
    __syncthreads();

    {
        int i = t & 31, c0 = t >> 5;
        float acc = 0.0f;
        #pragma unroll
        for (int c = c0; c < C; c += 8) { float v = s[c][i]; acc += v * v; }
        ps[c0][i] = acc;
    }
    __syncthreads();
    if (t < 32) {
        float sum = 0.0f;
        #pragma unroll
        for (int r = 0; r < 8; r++) sum += ps[r][t];
        inv[t] = 1.0f / fmaxf(sqrtf(sum), 1e-12f);
    }
    __syncthreads();

    __half* dst = (p == 0 ? g_qh : g_kh) + ((size_t)b * HW + hw0) * C;
    #pragma unroll
    for (int iter = 0; iter < 16; iter++) {
        int e  = t + iter * 256;
        int ii = e >> 7, c = e & 127;
        dst[ii * C + c] = __float2half(s[c][ii] * inv[ii]);
    }
}

// One block (128 thr) per query row n.
// Phase 1: bulk-gather the 129 key rows (slot 0 = positive, 1..128 = negs)
//          into smem, 16 lanes x 16 B per row, coalesced, high MLP.
// Phase 2: thread t computes the FULL dot for slot t from smem (thread 0
//          also slot 128) -- no shuffles, no gather latency on the critical
//          path. Rows padded to 17 uint4 (272 B): bank = 4*((slot+chunk)%8),
//          distinct across any 8 consecutive slots -> conflict-free reads.
// Online exp-sum (|logit| <= 1/0.07 -> fp32-exact, no max pass).
__global__ __launch_bounds__(128) void pnce_kernel(
        const int* __restrict__ negi, float* __restrict__ out) {
    __shared__ uint4 skey[129 * 17];   // 35088 B, padded rows
    __shared__ uint4 sq[16];           // query row, 256 B
    __shared__ float red[4];

    const int t    = threadIdx.x;
    const int w    = t >> 5;
    const int lane = t & 31;
    const int n    = blockIdx.x;

    // Stage query row (broadcast source for phase 2).
    if (t < 16)
        sq[t] = reinterpret_cast<const uint4*>(g_qh + (size_t)n * C)[t];

    // Gather keys: lane group of 16 covers one row (chunk = t&15).
    {
        const int c = t & 15;
        for (int s = t >> 4; s < 129; s += 8) {
            const int idx = (s == 0) ? n : negi[n * K + s - 1];
            skey[s * 17 + c] =
                reinterpret_cast<const uint4*>(g_kh + (size_t)idx * C)[c];
        }
    }
    __syncthreads();

    float esum = 0.0f;
    float lpos = 0.0f;                 // thread 0 only (slot 0)

    for (int slot = t; slot < 129; slot += 128) {
        __half2 a0 = __float2half2_rn(0.0f);
        __half2 a1 = __float2half2_rn(0.0f);
        __half2 a2 = __float2half2_rn(0.0f);
        __half2 a3 = __float2half2_rn(0.0f);
        const uint4* krow = &skey[slot * 17];
        #pragma unroll
        for (int i = 0; i < 16; i++) {
            const uint4 qv = sq[i];        // broadcast LDS
            const uint4 kv = krow[i];      // conflict-free LDS
            const __half2* qh = reinterpret_cast<const __half2*>(&qv);
            const __half2* kh = reinterpret_cast<const __half2*>(&kv);
            a0 = __hfma2(qh[0], kh[0], a0);
            a1 = __hfma2(qh[1], kh[1], a1);
            a2 = __hfma2(qh[2], kh[2], a2);
            a3 = __hfma2(qh[3], kh[3], a3);
        }
        const float2 f0 = __half22float2(a0);
        const float2 f1 = __half22float2(a1);
        const float2 f2 = __half22float2(a2);
        const float2 f3 = __half22float2(a3);
        const float d = (f0.x + f0.y) + (f1.x + f1.y)
                      + (f2.x + f2.y) + (f3.x + f3.y);
        const float lg = d * INV_TEMP;
        esum += __expf(lg);
        if (slot == 0) lpos = lg;      // only thread 0, first iteration
    }

    // Block reduce esum (lanes re-converged after the loop).
    esum += __shfl_xor_sync(0xffffffffu, esum, 16);
    esum += __shfl_xor_sync(0xffffffffu, esum, 8);
    esum += __shfl_xor_sync(0xffffffffu, esum, 4);
    esum += __shfl_xor_sync(0xffffffffu, esum, 2);
    esum += __shfl_xor_sync(0xffffffffu, esum, 1);
    if (lane == 0) red[w] = esum;
    __syncthreads();

    if (t == 0) {
        const float total = red[0] + red[1] + red[2] + red[3];
        atomicAdd(out, (__logf(total) - lpos) * (1.0f / (float)N));
    }
}

extern "C" void kernel_launch(void* const* d_in, const int* in_sizes, int n_in,
                              void* d_out, int out_size) {
    const float* feat_q = (const float*)d_in[0];
    const float* feat_k = (const float*)d_in[1];
    const int*   negi   = (const int*)d_in[2];
    float*       out    = (float*)d_out;

    // Best-effort: maximize smem carveout so ~6 blocks/SM can be resident.
    static int carveout_set = 0;
    if (!carveout_set) {
        cudaFuncSetAttribute(pnce_kernel,
                             cudaFuncAttributePreferredSharedMemoryCarveout,
                             100);
        carveout_set = 1;
    }

    normalize_kernel<<<256, 256>>>(feat_q, feat_k, out);
    pnce_kernel<<<N, 128>>>(negi, out);
}

// round 14
// speedup vs baseline: 1.3886x; 1.3886x over previous
#include <cuda_runtime.h>
#include <cuda_fp16.h>
#include <math.h>

#define C   128
#define HW  1024
#define N   4096
#define K   128
#define INV_TEMP (1.0f/0.07f)

// Scratch: normalized row-major [N, C] fp16 features (1 MB each).
__device__ __align__(16) __half g_qh[N * C];
__device__ __align__(16) __half g_kh[N * C];

// One block per (tensor p, batch b, 32-wide hw chunk): 2*4*32 = 256 blocks.
__global__ void normalize_kernel(const float* __restrict__ fq,
                                 const float* __restrict__ fk,
                                 float* __restrict__ out) {
    __shared__ float s[C][33];
    __shared__ float ps[8][32];
    __shared__ float inv[32];

    if (blockIdx.x == 0 && threadIdx.x == 0) out[0] = 0.0f;

    const int p   = blockIdx.x >> 7;          // 0 = q, 1 = k
    const int b   = (blockIdx.x >> 5) & 3;
    const int hw0 = (blockIdx.x & 31) << 5;
    const int t   = threadIdx.x;

    const float* src = (p == 0 ? fq : fk) + (size_t)b * C * HW + hw0;

    #pragma unroll
    for (int iter = 0; iter < 16; iter++) {
        int e = t + iter * 256;
        int c = e >> 5, i = e & 31;
        s[c][i] = src[c * HW + i];
    }
    __syncthreads();

    {
        int i = t & 31, c0 = t >> 5;
        float acc = 0.0f;
        #pragma unroll
        for (int c = c0; c < C; c += 8) { float v = s[c][i]; acc += v * v; }
        ps[c0][i] = acc;
    }
    __syncthreads();
    if (t < 32) {
        float sum = 0.0f;
        #pragma unroll
        for (int r = 0; r < 8; r++) sum += ps[r][t];
        inv[t] = 1.0f / fmaxf(sqrtf(sum), 1e-12f);
    }
    __syncthreads();

    __half* dst = (p == 0 ? g_qh : g_kh) + ((size_t)b * HW + hw0) * C;
    #pragma unroll
    for (int iter = 0; iter < 16; iter++) {
        int e  = t + iter * 256;
        int ii = e >> 7, c = e & 127;
        dst[ii * C + c] = __float2half(s[c][ii] * inv[ii]);
    }
}

// One block (128 thr) per query row n. Decoupled gather->compute:
//  Phase 0: stage the 136-slot index table into smem (slot 0 = positive,
//           1..128 = negatives, 129..135 = dummies idx n).
//  Phase 1: bulk-gather all 136 key rows into smem. Indices come from smem,
//           so the 17 LDG.128 per thread are fully independent (high MLP).
//  Phase 2: thread t computes the ENTIRE dot for slot t (and 128+t if t<8)
//           from smem -- no shuffles, no gather latency on the dot path.
//           Row stride 272 B => per-quarter-warp banks 4*lane: conflict-free.
// Dummies each contribute bitwise exp(lpos); subtract 7*exp(lpos) at the end.
// Online exp-sum (|logit| <= 1/0.07 -> fp32-exact, no max pass).
__global__ __launch_bounds__(128) void pnce_kernel(
        const int* __restrict__ negi, float* __restrict__ out) {
    __shared__ uint4 skey[136 * 17];   // 36992 B, padded rows (272 B each)
    __shared__ uint4 sq[16];           // query row, 256 B
    __shared__ int   sidx[136];
    __shared__ float red[4];

    const int t    = threadIdx.x;
    const int w    = t >> 5;
    const int lane = t & 31;
    const int n    = blockIdx.x;

    // Phase 0: stage indices (coalesced) + query row.
    sidx[t] = (t == 0) ? n : negi[n * K + t - 1];
    if (t < 8) sidx[128 + t] = (t == 0) ? negi[n * K + 127] : n;
    if (t < 16)
        sq[t] = reinterpret_cast<const uint4*>(g_qh + (size_t)n * C)[t];
    __syncthreads();

    // Phase 1: gather. Group g (t>>4) stages slots {g, g+8, ..., g+128}:
    // 17 independent LDS->LDG.128->STS chains per thread.
    {
        const int c = t & 15;
        const int g = t >> 4;
        #pragma unroll 4
        for (int it = 0; it < 17; it++) {
            const int s = g + (it << 3);
            const int idx = sidx[s];
            skey[s * 17 + c] =
                reinterpret_cast<const uint4*>(g_kh + (size_t)idx * C)[c];
        }
    }
    __syncthreads();

    // Phase 2: dense per-thread dots from smem.
    float esum = 0.0f;
    float lpos = 0.0f;                 // thread 0 only (slot 0)

    for (int pass = 0; pass < 2; pass++) {
        const int slot = t + (pass << 7);
        if (slot < 136) {
            __half2 a0 = __float2half2_rn(0.0f);
            __half2 a1 = __float2half2_rn(0.0f);
            __half2 a2 = __float2half2_rn(0.0f);
            __half2 a3 = __float2half2_rn(0.0f);
            const uint4* krow = &skey[slot * 17];
            #pragma unroll 4
            for (int i = 0; i < 16; i++) {
                const uint4 qv = sq[i];        // broadcast LDS
                const uint4 kv = krow[i];      // conflict-free LDS
                const __half2* qh = reinterpret_cast<const __half2*>(&qv);
                const __half2* kh = reinterpret_cast<const __half2*>(&kv);
                a0 = __hfma2(qh[0], kh[0], a0);
                a1 = __hfma2(qh[1], kh[1], a1);
                a2 = __hfma2(qh[2], kh[2], a2);
                a3 = __hfma2(qh[3], kh[3], a3);
            }
            const float2 f0 = __half22float2(a0);
            const float2 f1 = __half22float2(a1);
            const float2 f2 = __half22float2(a2);
            const float2 f3 = __half22float2(a3);
            const float d = (f0.x + f0.y) + (f1.x + f1.y)
                          + (f2.x + f2.y) + (f3.x + f3.y);
            const float lg = d * INV_TEMP;
            esum += __expf(lg);
            if (slot == 0) lpos = lg;  // thread 0, pass 0
        }
    }

    // Block reduce (warps fully converged here; full-mask shfls).
    esum += __shfl_xor_sync(0xffffffffu, esum, 16);
    esum += __shfl_xor_sync(0xffffffffu, esum, 8);
    esum += __shfl_xor_sync(0xffffffffu, esum, 4);
    esum += __shfl_xor_sync(0xffffffffu, esum, 2);
    esum += __shfl_xor_sync(0xffffffffu, esum, 1);
    if (lane == 0) red[w] = esum;
    __syncthreads();

    if (t == 0) {
        // Remove the 7 dummy contributions (each bitwise == exp(lpos)).
        const float total = (red[0] + red[1] + red[2] + red[3])
                          - 7.0f * __expf(lpos);
        atomicAdd(out, (__logf(total) - lpos) * (1.0f / (float)N));
    }
}

extern "C" void kernel_launch(void* const* d_in, const int* in_sizes, int n_in,
                              void* d_out, int out_size) {
    const float* feat_q = (const float*)d_in[0];
    const float* feat_k = (const float*)d_in[1];
    const int*   negi   = (const int*)d_in[2];
    float*       out    = (float*)d_out;

    static int carveout_set = 0;
    if (!carveout_set) {
        cudaFuncSetAttribute(pnce_kernel,
                             cudaFuncAttributePreferredSharedMemoryCarveout,
                             100);
        carveout_set = 1;
    }

    normalize_kernel<<<256, 256>>>(feat_q, feat_k, out);
    pnce_kernel<<<N, 128>>>(negi, out);
}

// round 15
// speedup vs baseline: 2.4443x; 1.7603x over previous
#include <cuda_runtime.h>
#include <cuda_fp16.h>
#include <math.h>

#define C   128
#define HW  1024
#define N   4096
#define K   128
#define INV_TEMP (1.0f/0.07f)

// Scratch: normalized row-major [N, C] fp16 features (1 MB each).
__device__ __align__(16) __half g_qh[N * C];
__device__ __align__(16) __half g_kh[N * C];

// One block per (tensor p, batch b, 32-wide hw chunk): 2*4*32 = 256 blocks.
__global__ void normalize_kernel(const float* __restrict__ fq,
                                 const float* __restrict__ fk,
                                 float* __restrict__ out) {
    __shared__ float s[C][33];
    __shared__ float ps[8][32];
    __shared__ float inv[32];

    if (blockIdx.x == 0 && threadIdx.x == 0) out[0] = 0.0f;

    const int p   = blockIdx.x >> 7;          // 0 = q, 1 = k
    const int b   = (blockIdx.x >> 5) & 3;
    const int hw0 = (blockIdx.x & 31) << 5;
    const int t   = threadIdx.x;

    const float* src = (p == 0 ? fq : fk) + (size_t)b * C * HW + hw0;

    #pragma unroll
    for (int iter = 0; iter < 16; iter++) {
        int e = t + iter * 256;
        int c = e >> 5, i = e & 31;
        s[c][i] = src[c * HW + i];
    }
    __syncthreads();

    {
        int i = t & 31, c0 = t >> 5;
        float acc = 0.0f;
        #pragma unroll
        for (int c = c0; c < C; c += 8) { float v = s[c][i]; acc += v * v; }
        ps[c0][i] = acc;
    }
    __syncthreads();
    if (t < 32) {
        float sum = 0.0f;
        #pragma unroll
        for (int r = 0; r < 8; r++) sum += ps[r][t];
        inv[t] = 1.0f / fmaxf(sqrtf(sum), 1e-12f);
    }
    __syncthreads();

    __half* dst = (p == 0 ? g_qh : g_kh) + ((size_t)b * HW + hw0) * C;
    #pragma unroll
    for (int iter = 0; iter < 16; iter++) {
        int e  = t + iter * 256;
        int ii = e >> 7, c = e & 127;
        dst[ii * C + c] = __float2half(s[c][ii] * inv[ii]);
    }
}

// Lane-local 16-element partial dot: one HFMA2 chain over 8 half2.
__device__ __forceinline__ float dot16h(const uint4& qv0, const uint4& qv1,
                                        const uint4& kv0, const uint4& kv1) {
    const __half2* q = reinterpret_cast<const __half2*>(&qv0);
    const __half2* Q = reinterpret_cast<const __half2*>(&qv1);
    const __half2* k = reinterpret_cast<const __half2*>(&kv0);
    const __half2* Kk = reinterpret_cast<const __half2*>(&kv1);
    __half2 acc = __hmul2(q[0], k[0]);
    acc = __hfma2(q[1], k[1], acc);
    acc = __hfma2(q[2], k[2], acc);
    acc = __hfma2(q[3], k[3], acc);
    acc = __hfma2(Q[0], Kk[0], acc);
    acc = __hfma2(Q[1], Kk[1], acc);
    acc = __hfma2(Q[2], Kk[2], acc);
    acc = __hfma2(Q[3], Kk[3], acc);
    const float2 f = __half22float2(acc);
    return f.x + f.y;
}

// 8-lane-group all-reduce on a fully converged warp: xor 4/2/1 stay inside
// the 8-lane group; every lane ends with its group's sum. Full mask.
__device__ __forceinline__ float group8_allsum(float p) {
    p += __shfl_xor_sync(0xffffffffu, p, 4);
    p += __shfl_xor_sync(0xffffffffu, p, 2);
    p += __shfl_xor_sync(0xffffffffu, p, 1);
    return p;
}

// FOUR warps per row, TWO rows per 256-thr block (grid 2048 -> 16384 warps,
// occupancy saturates the 64-warp/SM cap). Slot table sidx[136]: 0 =
// positive (idx n), 1..128 = negatives, 129..135 = dummies (idx n; each
// contributes bitwise exp(lpos), subtracted at the end). Warp q covers
// slots [32q, 32q+32) in 4 trips of 8 (2 per 8-lane group); warp 0 runs a
// 5th trip over slots 128..135. Divergence only ACROSS warps; all shfls
// full-mask on converged warps. Online exp-sum (|logit| <= 1/0.07 ->
// fp32-exact, no max pass). Each warp stages and reads only its own table
// range -> __syncwarp suffices until the final combine.
__global__ __launch_bounds__(256) void pnce_kernel(
        const int* __restrict__ negi, float* __restrict__ out) {
    __shared__ int   sidx[2][136];
    __shared__ float spart[2][4];

    const int t    = threadIdx.x;
    const int w    = t >> 5;
    const int lane = t & 31;
    const int r    = w >> 2;        // row within block: 0/1
    const int q    = w & 3;         // warp within row: 0..3
    const int g    = lane >> 3;     // group 0..3
    const int l8   = lane & 7;      // lane within group
    const int n    = (blockIdx.x << 1) + r;

    // Stage this warp's slot range.
    if (q == 0) {
        sidx[r][lane] = (lane == 0) ? n : negi[n * K + lane - 1];
        if (lane < 8)
            sidx[r][128 + lane] = (lane == 0) ? negi[n * K + 127] : n;
    } else {
        sidx[r][32 * q + lane] = negi[n * K + 32 * q + lane - 1];
    }
    __syncwarp();

    const uint4* qptr = reinterpret_cast<const uint4*>(g_qh + (size_t)n * C);
    const uint4 qv0 = qptr[l8];
    const uint4 qv1 = qptr[l8 + 8];

    // Lane's byte base into the key table; row offset = idx << 8.
    const char* kb = reinterpret_cast<const char*>(g_kh) + l8 * 16;

    float s    = 0.0f;
    float lpos = 0.0f;              // meaningful only on warp 0

    const int trips = (q == 0) ? 5 : 4;     // cross-warp divergence only
    for (int T = 0; T < trips; T++) {
        const int base = (T == 4) ? 128 : (32 * q + T * 8);
        const int j1 = base + g;
        const int i1 = sidx[r][j1];
        const int i2 = sidx[r][j1 + 4];

        const uint4* p1 =
            reinterpret_cast<const uint4*>(kb + ((size_t)(unsigned)i1 << 8));
        const uint4* p2 =
            reinterpret_cast<const uint4*>(kb + ((size_t)(unsigned)i2 << 8));
        const uint4 a0 = p1[0];
        const uint4 a1 = p1[8];     // +128 bytes
        const uint4 b0 = p2[0];
        const uint4 b1 = p2[8];

        const float d1 = group8_allsum(dot16h(qv0, qv1, a0, a1));
        const float d2 = group8_allsum(dot16h(qv0, qv1, b0, b1));

        const float l1 = d1 * INV_TEMP;
        const float l2 = d2 * INV_TEMP;
        s += __expf(l1) + __expf(l2);
        if (j1 == 0) lpos = l1;     // SEL; true once (warp 0, T0, g0)
    }

    // Cross-group combine (groups hold identical sums; each counted once).
    s += __shfl_xor_sync(0xffffffffu, s, 8);
    s += __shfl_xor_sync(0xffffffffu, s, 16);
    if (lane == 0) spart[r][q] = s;
    __syncthreads();

    // Combiner = warp 0 lane 0 of each row; it already holds lpos.
    if (q == 0 && lane == 0) {
        const float total = spart[r][0] + spart[r][1] + spart[r][2]
                          + spart[r][3] - 7.0f * __expf(lpos);
        atomicAdd(out, (__logf(total) - lpos) * (1.0f / (float)N));
    }
}

extern "C" void kernel_launch(void* const* d_in, const int* in_sizes, int n_in,
                              void* d_out, int out_size) {
    const float* feat_q = (const float*)d_in[0];
    const float* feat_k = (const float*)d_in[1];
    const int*   negi   = (const int*)d_in[2];
    float*       out    = (float*)d_out;

    normalize_kernel<<<256, 256>>>(feat_q, feat_k, out);
    pnce_kernel<<<N / 2, 256>>>(negi, out);
}

// round 16
// speedup vs baseline: 2.6817x; 1.0972x over previous
#include <cuda_runtime.h>
#include <cuda_fp16.h>
#include <math.h>

#define C   128
#define HW  1024
#define N   4096
#define K   128
#define INV_TEMP (1.0f/0.07f)

// Scratch: normalized row-major [N, C] fp16 features (1 MB each) + positive
// logits (fp32, logit units) computed in the normalize pass.
__device__ __align__(16) __half g_qh[N * C];
__device__ __align__(16) __half g_kh[N * C];
__device__ float g_lpos[N];

// One block per (batch b, 32-wide hw chunk): 128 blocks, 256 threads.
// Both q and k tiles live in smem simultaneously, so the positive logit
// l_pos = (q/||q||)·(k/||k||) is computed here in fp32 for free.
__global__ void normalize_kernel(const float* __restrict__ fq,
                                 const float* __restrict__ fk,
                                 float* __restrict__ out) {
    __shared__ float sQ[C][33];
    __shared__ float sK[C][33];
    __shared__ float psq[8][32];
    __shared__ float psk[8][32];
    __shared__ float psd[8][32];
    __shared__ float invq[32], invk[32];

    if (blockIdx.x == 0 && threadIdx.x == 0) out[0] = 0.0f;

    const int b   = blockIdx.x >> 5;
    const int hw0 = (blockIdx.x & 31) << 5;
    const int t   = threadIdx.x;

    const float* srcq = fq + (size_t)b * C * HW + hw0;
    const float* srck = fk + (size_t)b * C * HW + hw0;

    // Load both C x 32 tiles, hw fastest (coalesced).
    #pragma unroll
    for (int iter = 0; iter < 16; iter++) {
        int e = t + iter * 256;
        int c = e >> 5, i = e & 31;
        sQ[c][i] = srcq[c * HW + i];
        sK[c][i] = srck[c * HW + i];
    }
    __syncthreads();

    // Partials over channels: sumsq(q), sumsq(k), dot(q,k) per hw position.
    {
        const int i = t & 31, c0 = t >> 5;
        float aq = 0.0f, ak = 0.0f, ad = 0.0f;
        #pragma unroll
        for (int c = c0; c < C; c += 8) {
            const float qv = sQ[c][i];
            const float kv = sK[c][i];
            aq += qv * qv;
            ak += kv * kv;
            ad += qv * kv;
        }
        psq[c0][i] = aq;
        psk[c0][i] = ak;
        psd[c0][i] = ad;
    }
    __syncthreads();
    if (t < 32) {
        float sq = 0.0f, sk = 0.0f, sd = 0.0f;
        #pragma unroll
        for (int r = 0; r < 8; r++) {
            sq += psq[r][t];
            sk += psk[r][t];
            sd += psd[r][t];
        }
        const float iq = 1.0f / fmaxf(sqrtf(sq), 1e-12f);
        const float ik = 1.0f / fmaxf(sqrtf(sk), 1e-12f);
        invq[t] = iq;
        invk[t] = ik;
        g_lpos[b * HW + hw0 + t] = sd * iq * ik * INV_TEMP;  // fp32-exact
    }
    __syncthreads();

    // Write transposed normalized fp16 rows (coalesced over c).
    const size_t base = ((size_t)b * HW + hw0) * C;
    #pragma unroll
    for (int iter = 0; iter < 16; iter++) {
        int e  = t + iter * 256;
        int ii = e >> 7, c = e & 127;
        g_qh[base + ii * C + c] = __float2half(sQ[c][ii] * invq[ii]);
        g_kh[base + ii * C + c] = __float2half(sK[c][ii] * invk[ii]);
    }
}

// Lane-local 16-element partial dot: one HFMA2 chain over 8 half2.
__device__ __forceinline__ float dot16h(const uint4& qv0, const uint4& qv1,
                                        const uint4& kv0, const uint4& kv1) {
    const __half2* q = reinterpret_cast<const __half2*>(&qv0);
    const __half2* Q = reinterpret_cast<const __half2*>(&qv1);
    const __half2* k = reinterpret_cast<const __half2*>(&kv0);
    const __half2* Kk = reinterpret_cast<const __half2*>(&kv1);
    __half2 acc = __hmul2(q[0], k[0]);
    acc = __hfma2(q[1], k[1], acc);
    acc = __hfma2(q[2], k[2], acc);
    acc = __hfma2(q[3], k[3], acc);
    acc = __hfma2(Q[0], Kk[0], acc);
    acc = __hfma2(Q[1], Kk[1], acc);
    acc = __hfma2(Q[2], Kk[2], acc);
    acc = __hfma2(Q[3], Kk[3], acc);
    const float2 f = __half22float2(acc);
    return f.x + f.y;
}

// 8-lane-group all-reduce on a fully converged warp: xor 4/2/1 stay inside
// the 8-lane group; every lane ends with its group's sum. Full mask.
__device__ __forceinline__ float group8_allsum(float p) {
    p += __shfl_xor_sync(0xffffffffu, p, 4);
    p += __shfl_xor_sync(0xffffffffu, p, 2);
    p += __shfl_xor_sync(0xffffffffu, p, 1);
    return p;
}

// FOUR warps per row, TWO rows per 256-thr block (grid 2048). The positive
// is handled in normalize, so pnce is PERFECTLY uniform: 128 negatives =
// 4 warps x 4 trips x 8 slots, no dummies, no special cases. Warp q covers
// slots [32q, 32q+32). Online exp-sum (|logit| <= 1/0.07 -> fp32-exact, no
// max pass). Each warp stages and reads only its own index range ->
// __syncwarp suffices until the final combine.
__global__ __launch_bounds__(256) void pnce_kernel(
        const int* __restrict__ negi, float* __restrict__ out) {
    __shared__ int   sidx[2][128];
    __shared__ float spart[2][4];

    const int t    = threadIdx.x;
    const int w    = t >> 5;
    const int lane = t & 31;
    const int r    = w >> 2;        // row within block: 0/1
    const int qw   = w & 3;         // warp within row: 0..3
    const int g    = lane >> 3;     // group 0..3
    const int l8   = lane & 7;      // lane within group
    const int n    = (blockIdx.x << 1) + r;

    // Combiner thread kicks off its lpos load early (latency hidden).
    float lpos = 0.0f;
    if (qw == 0 && lane == 0) lpos = g_lpos[n];

    // Stage this warp's 32 negative indices (coalesced).
    sidx[r][32 * qw + lane] = negi[n * K + 32 * qw + lane];
    __syncwarp();

    const uint4* qptr = reinterpret_cast<const uint4*>(g_qh + (size_t)n * C);
    const uint4 qv0 = qptr[l8];
    const uint4 qv1 = qptr[l8 + 8];

    // Lane's byte base into the key table; row offset = idx << 8.
    const char* kb = reinterpret_cast<const char*>(g_kh) + l8 * 16;

    float s = 0.0f;

    #pragma unroll 1
    for (int T = 0; T < 4; T++) {
        const int j1 = 32 * qw + T * 8 + g;
        const int i1 = sidx[r][j1];
        const int i2 = sidx[r][j1 + 4];

        const uint4* p1 =
            reinterpret_cast<const uint4*>(kb + ((size_t)(unsigned)i1 << 8));
        const uint4* p2 =
            reinterpret_cast<const uint4*>(kb + ((size_t)(unsigned)i2 << 8));
        const uint4 a0 = p1[0];
        const uint4 a1 = p1[8];     // +128 bytes
        const uint4 b0 = p2[0];
        const uint4 b1 = p2[8];

        const float d1 = group8_allsum(dot16h(qv0, qv1, a0, a1));
        const float d2 = group8_allsum(dot16h(qv0, qv1, b0, b1));

        s += __expf(d1 * INV_TEMP) + __expf(d2 * INV_TEMP);
    }

    // Cross-group combine (groups hold identical sums; each counted once).
    s += __shfl_xor_sync(0xffffffffu, s, 8);
    s += __shfl_xor_sync(0xffffffffu, s, 16);
    if (lane == 0) spart[r][qw] = s;
    __syncthreads();

    if (qw == 0 && lane == 0) {
        const float total = spart[r][0] + spart[r][1] + spart[r][2]
                          + spart[r][3] + __expf(lpos);
        atomicAdd(out, (__logf(total) - lpos) * (1.0f / (float)N));
    }
}

extern "C" void kernel_launch(void* const* d_in, const int* in_sizes, int n_in,
                              void* d_out, int out_size) {
    const float* feat_q = (const float*)d_in[0];
    const float* feat_k = (const float*)d_in[1];
    const int*   negi   = (const int*)d_in[2];
    float*       out    = (float*)d_out;

    normalize_kernel<<<128, 256>>>(feat_q, feat_k, out);
    pnce_kernel<<<N / 2, 256>>>(negi, out);
}